// round 4
// baseline (speedup 1.0000x reference)
#include <cuda_runtime.h>
#include <math.h>
#include <stdint.h>

#define NROWS 4096
#define DIMH  1024
#define DIN2  2048

// ---------------- device helpers ----------------
__device__ __forceinline__ float srelu(float x){
    float r = fmaxf(x, 0.0f);
    if (r < 0.1f){ float r2 = r*r; return (0.2f*r*r2 - r2*r2) * 500.0f; }
    return x - 0.05f;
}
__device__ __forceinline__ float softplusf(float x){
    return fmaxf(x, 0.0f) + log1pf(expf(-fabsf(x)));
}

// ---------------- scratch (device globals) ----------------
__device__ float g_Pt  [DIMH*DIMH];
__device__ float g_PtSc[DIMH*DIMH];
__device__ float g_Lm  [DIMH*DIMH];
__device__ float g_Hu  [NROWS*DIMH];
__device__ float g_st  [NROWS*DIN2];
__device__ float g_G1  [NROWS*DIMH];
__device__ float g_icWcat[128*DIN2];
__device__ float g_H1  [NROWS*512];
__device__ float g_H2  [NROWS*512];
__device__ float g_CT  [NROWS*DIN2];
__device__ float g_Z01 [NROWS*128];
__device__ float g_Z2  [NROWS*64];
__device__ float g_spU0[64*64];
__device__ float g_spU1[64];
__device__ float g_cb01[128];
__device__ float g_z0[1];

// ---------------- fused P transpose + eig scale ----------------
__global__ void transposePK(const float* __restrict__ P, const float* __restrict__ t,
                            float* __restrict__ Pt, float* __restrict__ PtSc){
    __shared__ float tile[32][33];
    int c0 = blockIdx.x*32, r0 = blockIdx.y*32;
    int x = threadIdx.x, y = threadIdx.y;
    float s = 2.0f * sinf(t[0]);
    #pragma unroll
    for (int i=0;i<32;i+=8)
        tile[y+i][x] = P[(size_t)(r0+y+i)*DIMH + c0 + x];
    __syncthreads();
    #pragma unroll
    for (int i=0;i<32;i+=8){
        int c = c0 + y + i;
        int r = r0 + x;
        float v = tile[x][y+i];
        float e = (r == 0) ? 0.0f : ((r <= 511) ? (1.0f + s) : (1.0f - s));
        Pt  [(size_t)c*DIMH + r] = v;
        PtSc[(size_t)c*DIMH + r] = e * v;
    }
}

// ---------------- concat icW0/icW1 ----------------
__global__ void catIcWK(const float* __restrict__ w0, const float* __restrict__ w1){
    int i = blockIdx.x*256 + threadIdx.x;
    g_icWcat[i]           = w0[i];
    g_icWcat[64*DIN2 + i] = w1[i];
}

// ---------------- Hu = sigmoid(10*u), st = x - x[col0 of half] (float4) ----------------
__global__ void huStK(const float* __restrict__ state){
    int idx = blockIdx.x*blockDim.x + threadIdx.x;   // over NROWS*512 float4s
    int n = idx >> 9, q = idx & 511;                 // q: float4 index in row
    const float4* s4 = reinterpret_cast<const float4*>(state);
    float4 x = s4[idx];
    float x0 = state[(n<<11) + (q < 256 ? 0 : DIMH)];
    float4 stv = make_float4(x.x-x0, x.y-x0, x.z-x0, x.w-x0);
    reinterpret_cast<float4*>(g_st)[idx] = stv;
    if (q < 256){
        float4 h;
        h.x = 1.0f/(1.0f + expf(-10.0f*x.x));
        h.y = 1.0f/(1.0f + expf(-10.0f*x.y));
        h.z = 1.0f/(1.0f + expf(-10.0f*x.z));
        h.w = 1.0f/(1.0f + expf(-10.0f*x.w));
        reinterpret_cast<float4*>(g_Hu)[n*256 + q] = h;
    }
}

// ---------------- softplus(U), concat biases, z0 constant ----------------
__global__ void prepIcnnK(const float* __restrict__ icU0, const float* __restrict__ icU1,
                          const float* __restrict__ icb0, const float* __restrict__ icb1,
                          const float* __restrict__ icb2){
    int tid = threadIdx.x;
    for (int i = tid; i < 64*64; i += blockDim.x) g_spU0[i] = softplusf(icU0[i]);
    if (tid < 64){
        g_spU1[tid]     = softplusf(icU1[tid]);
        g_cb01[tid]     = icb0[tid];
        g_cb01[64+tid]  = icb1[tid];
    }
    __syncthreads();
    __shared__ float z0a[64], z0b[64];
    if (tid < 64) z0a[tid] = srelu(icb0[tid]);
    __syncthreads();
    if (tid < 64){
        float s = icb1[tid];
        #pragma unroll 8
        for (int j=0;j<64;j++) s += g_spU0[tid*64+j]*z0a[j];
        z0b[tid] = srelu(s);
    }
    __syncthreads();
    if (tid == 0){
        float s = icb2[0];
        for (int j=0;j<64;j++) s += g_spU1[j]*z0b[j];
        g_z0[0] = srelu(s);
    }
}

// ---------------- z2: 4 rows per block, smem-cached transposed spU0 ----------------
__global__ void z2K(){
    __shared__ float sUT[64*64];    // sUT[j*64+k] = spU0[k][j]
    __shared__ float z1s[4][64];
    int t = threadIdx.x;            // 256
    for (int i = t; i < 4096; i += 256){
        int j = i >> 6, k = i & 63;
        sUT[i] = g_spU0[k*64 + j];
    }
    int r = t >> 6, k = t & 63;
    int n = blockIdx.x*4 + r;
    z1s[r][k] = srelu(g_Z01[n*128 + k]);
    __syncthreads();
    float s = g_Z01[n*128 + 64 + k];
    #pragma unroll 8
    for (int j=0;j<64;j++) s += sUT[j*64 + k]*z1s[r][j];
    g_Z2[n*64 + k] = srelu(s);
}

// ---------------- final assembly ----------------
__global__ void finalK(const float* __restrict__ state, const float* __restrict__ icW2,
                       const float* __restrict__ icb2, float* __restrict__ out){
    int n = blockIdx.x;
    int tid = threadIdx.x;  // 256
    const float* srow = state + (size_t)n*DIN2;
    const float4* srow4 = reinterpret_cast<const float4*>(srow);
    const float4* icW24 = reinterpret_cast<const float4*>(icW2);
    const float4* CT4   = reinterpret_cast<const float4*>(g_CT + (size_t)n*DIN2);

    float x0u = srow[0], x0v = srow[DIMH];

    float dot = 0.0f, ss = 0.0f;
    #pragma unroll
    for (int it=0; it<2; it++){
        int q = tid + it*256;
        float4 x = srow4[q], w = icW24[q];
        dot += w.x*x.x + w.y*x.y + w.z*x.z + w.w*x.w;
        ss  += x.x*x.x + x.y*x.y + x.z*x.z + x.w*x.w;
    }
    #pragma unroll
    for (int o=16;o>0;o>>=1){
        dot += __shfl_down_sync(0xffffffffu, dot, o);
        ss  += __shfl_down_sync(0xffffffffu, ss,  o);
    }
    __shared__ float sd[8], sq[8];
    if ((tid & 31) == 0){ sd[tid>>5] = dot; sq[tid>>5] = ss; }
    __syncthreads();
    if (tid == 0){
        float D = 0.0f, S = 0.0f;
        #pragma unroll
        for (int w=0;w<8;w++){ D += sd[w]; S += sq[w]; }
        float z = icb2[0] + D;
        for (int k=0;k<64;k++) z = fmaf(g_spU1[k], g_Z2[n*64+k], z);
        float z3 = srelu(z);
        out[(size_t)n*2049 + 2048] = srelu(z3 - g_z0[0]) + 0.001f*S;
    }

    #pragma unroll
    for (int it=0; it<2; it++){
        int q = tid + it*256;          // float4 index; d = 4q
        int d = q*4;
        float4 x  = srow4[q];
        float4 ct = CT4[q];
        float x0 = (d < DIMH) ? x0u : x0v;
        float r[4];
        float xv[4] = {x.x, x.y, x.z, x.w};
        float cv[4] = {ct.x, ct.y, ct.z, ct.w};
        if (d < DIMH){
            const float4 v4 = srow4[q + 256];       // matching v values
            const float4 gg = reinterpret_cast<const float4*>(g_G1 + (size_t)n*DIMH)[q];
            float vv[4] = {v4.x, v4.y, v4.z, v4.w};
            float gv[4] = {gg.x, gg.y, gg.z, gg.w};
            #pragma unroll
            for (int e=0;e<4;e++){
                float ux = cv[e]*(xv[e]-x0);
                float ctrl = (ux < 10.0f && ux > -10.0f) ? ux : 0.0f;
                float uu = xv[e];
                r[e] = uu - uu*uu*uu*(1.0f/3.0f) - vv[e] + 1.0f + gv[e] + ctrl;
            }
        } else {
            const float4 u4 = srow4[q - 256];
            float uv[4] = {u4.x, u4.y, u4.z, u4.w};
            #pragma unroll
            for (int e=0;e<4;e++){
                float ux = cv[e]*(xv[e]-x0);
                float ctrl = (ux < 10.0f && ux > -10.0f) ? ux : 0.0f;
                r[e] = 0.2f*(uv[e] + 0.7f - 0.8f*xv[e]) + ctrl;
            }
        }
        float* o = out + (size_t)n*2049 + d;
        o[0]=r[0]; o[1]=r[1]; o[2]=r[2]; o[3]=r[3];
    }
}

// ---------------- 3xTF32 tensor-core GEMM, 4-stage cp.async pipeline ----------------
#define CPASYNC(dst, src) asm volatile("cp.async.cg.shared.global [%0], [%1], 16;\n" :: "r"(dst), "l"(src))
#define CPCOMMIT()        asm volatile("cp.async.commit_group;\n" ::: "memory")
#define CPWAIT(n)         asm volatile("cp.async.wait_group %0;\n" :: "n"(n) : "memory")

__device__ __forceinline__ void ldsm4(uint32_t addr, uint32_t& r0, uint32_t& r1,
                                      uint32_t& r2, uint32_t& r3){
    asm volatile("ldmatrix.sync.aligned.m8n8.x4.shared.b16 {%0,%1,%2,%3}, [%4];"
                 : "=r"(r0), "=r"(r1), "=r"(r2), "=r"(r3) : "r"(addr));
}
__device__ __forceinline__ uint32_t f2tf32(float x){
    uint32_t r; asm("cvt.rna.tf32.f32 %0, %1;" : "=r"(r) : "f"(x)); return r;
}
__device__ __forceinline__ void split32(uint32_t v, uint32_t& hi, uint32_t& lo){
    float x = __uint_as_float(v);
    hi = f2tf32(x);
    lo = f2tf32(x - __uint_as_float(hi));
}
__device__ __forceinline__ void mma_tf32(float* d, const uint32_t* a4,
                                         uint32_t b0, uint32_t b1){
    asm volatile("mma.sync.aligned.m16n8k8.row.col.f32.tf32.tf32.f32 "
                 "{%0,%1,%2,%3}, {%4,%5,%6,%7}, {%8,%9}, {%0,%1,%2,%3};"
                 : "+f"(d[0]), "+f"(d[1]), "+f"(d[2]), "+f"(d[3])
                 : "r"(a4[0]), "r"(a4[2]), "r"(a4[1]), "r"(a4[3]),
                   "r"(b0), "r"(b1));
}

// C[M,N] = A[M,K] @ Bt[N,K]^T (+bias, EPI 0/1=tanh). M%BM==0, N%BN==0, K%16==0.
template<int BM, int BN, int EPI>
__global__ __launch_bounds__(256)
void mmaGemm(int M, int N, int K,
             const float* __restrict__ A, const float* __restrict__ Bt,
             const float* __restrict__ bias, float* __restrict__ C){
    constexpr int BK  = 16;
    constexpr int LDS = BK + 4;
    constexpr int STAGES = 4;
    constexpr int WARPS_M = BM/32;
    constexpr int WARPS_N = 8/WARPS_M;
    constexpr int WN = BN/WARPS_N;
    constexpr int NP = WN/16;

    extern __shared__ __align__(16) float smem[];
    float* As = smem;                       // STAGES * BM * LDS
    float* Bs = smem + STAGES*BM*LDS;       // STAGES * BN * LDS

    const int tid  = threadIdx.x;
    const int warp = tid >> 5, lane = tid & 31;
    const int wm = (warp % WARPS_M)*32;
    const int wn = (warp / WARPS_M)*WN;
    const int bm = blockIdx.y*BM, bn = blockIdx.x*BN;

    const int lrow   = ((lane>>4)&1)*8 + (lane&7);
    const int lcol16 = ((lane>>3)&1)*16;

    float acc[2][2*NP][4];
    #pragma unroll
    for (int i=0;i<2;i++)
        #pragma unroll
        for (int j=0;j<2*NP;j++)
            #pragma unroll
            for (int q=0;q<4;q++) acc[i][j][q] = 0.0f;

    const float* Ag = A  + (size_t)bm*K;
    const float* Bg = Bt + (size_t)bn*K;
    uint32_t asBase = (uint32_t)__cvta_generic_to_shared(As);
    uint32_t bsBase = (uint32_t)__cvta_generic_to_shared(Bs);

    const int nk = K / BK;

    auto loadTile = [&](int buf, int k0){
        uint32_t aB = asBase + buf*(BM*LDS*4);
        #pragma unroll
        for (int i=0;i<(BM*4)/256;i++){
            int L = tid + i*256;
            int r = L>>2, s = L&3;
            CPASYNC(aB + (r*LDS + s*4)*4, Ag + (size_t)r*K + k0 + s*4);
        }
        uint32_t bB = bsBase + buf*(BN*LDS*4);
        #pragma unroll
        for (int i=0;i<(BN*4)/256;i++){
            int L = tid + i*256;
            int r = L>>2, s = L&3;
            CPASYNC(bB + (r*LDS + s*4)*4, Bg + (size_t)r*K + k0 + s*4);
        }
        CPCOMMIT();
    };

    // prologue: STAGES-1 tiles in flight
    #pragma unroll
    for (int p=0; p<STAGES-1; p++){
        if (p < nk) loadTile(p, p*BK); else CPCOMMIT();
    }

    for (int ck = 0; ck < nk; ck++){
        CPWAIT(STAGES-2);
        __syncthreads();

        // prefetch tile ck+STAGES-1 into buffer computed 1 iter ago (safe after barrier)
        int nxt = ck + STAGES - 1;
        if (nxt < nk) loadTile(nxt % STAGES, nxt*BK); else CPCOMMIT();

        int buf = ck % STAGES;
        uint32_t aB = asBase + buf*(BM*LDS*4);
        uint32_t bB = bsBase + buf*(BN*LDS*4);
        #pragma unroll
        for (int s=0; s<2; s++){
            uint32_t bhi[NP][4], blo[NP][4];
            #pragma unroll
            for (int p=0; p<NP; p++){
                uint32_t r0,r1,r2,r3;
                ldsm4(bB + (uint32_t)((wn + p*16 + lrow)*LDS*4) + lcol16 + s*32, r0,r1,r2,r3);
                split32(r0, bhi[p][0], blo[p][0]);
                split32(r1, bhi[p][1], blo[p][1]);
                split32(r2, bhi[p][2], blo[p][2]);
                split32(r3, bhi[p][3], blo[p][3]);
            }
            #pragma unroll
            for (int mt=0; mt<2; mt++){
                uint32_t r0,r1,r2,r3;
                uint32_t ahi[4], alo[4];
                ldsm4(aB + (uint32_t)((wm + mt*16 + lrow)*LDS*4) + lcol16 + s*32, r0,r1,r2,r3);
                split32(r0, ahi[0], alo[0]);
                split32(r1, ahi[1], alo[1]);
                split32(r2, ahi[2], alo[2]);
                split32(r3, ahi[3], alo[3]);
                #pragma unroll
                for (int p=0; p<NP; p++){
                    mma_tf32(acc[mt][2*p+0], ahi, bhi[p][0], bhi[p][1]);
                    mma_tf32(acc[mt][2*p+0], alo, bhi[p][0], bhi[p][1]);
                    mma_tf32(acc[mt][2*p+0], ahi, blo[p][0], blo[p][1]);
                    mma_tf32(acc[mt][2*p+1], ahi, bhi[p][2], bhi[p][3]);
                    mma_tf32(acc[mt][2*p+1], alo, bhi[p][2], bhi[p][3]);
                    mma_tf32(acc[mt][2*p+1], ahi, blo[p][2], blo[p][3]);
                }
            }
        }
        __syncthreads();
    }

    const int tg = lane & 3, g = lane >> 2;
    #pragma unroll
    for (int mt=0; mt<2; mt++){
        #pragma unroll
        for (int nt=0; nt<2*NP; nt++){
            int row = bm + wm + mt*16 + g;
            int col = bn + wn + nt*8 + tg*2;
            float v0 = acc[mt][nt][0], v1 = acc[mt][nt][1];
            float v2 = acc[mt][nt][2], v3 = acc[mt][nt][3];
            if (bias){
                float b0v = bias[col], b1v = bias[col+1];
                v0 += b0v; v1 += b1v; v2 += b0v; v3 += b1v;
            }
            if (EPI == 1){ v0 = tanhf(v0); v1 = tanhf(v1); v2 = tanhf(v2); v3 = tanhf(v3); }
            *reinterpret_cast<float2*>(C + (size_t)row*N + col)     = make_float2(v0, v1);
            *reinterpret_cast<float2*>(C + (size_t)(row+8)*N + col) = make_float2(v2, v3);
        }
    }
}

// ---------------- host ----------------
extern "C" void kernel_launch(void* const* d_in, const int* in_sizes, int n_in,
                              void* d_out, int out_size){
    const float* state = (const float*)d_in[0];
    const float* t     = (const float*)d_in[1];
    const float* P     = (const float*)d_in[2];
    const float* W1    = (const float*)d_in[3];
    const float* b1    = (const float*)d_in[4];
    const float* W2    = (const float*)d_in[5];
    const float* b2    = (const float*)d_in[6];
    const float* W3    = (const float*)d_in[7];
    const float* b3    = (const float*)d_in[8];
    const float* icW0  = (const float*)d_in[9];
    const float* icb0  = (const float*)d_in[10];
    const float* icW1  = (const float*)d_in[11];
    const float* icb1  = (const float*)d_in[12];
    const float* icW2  = (const float*)d_in[13];
    const float* icb2  = (const float*)d_in[14];
    const float* icU0  = (const float*)d_in[15];
    const float* icU1  = (const float*)d_in[16];
    float* out = (float*)d_out;

    float *Pt, *PtSc, *Lm, *Hu, *st, *G1, *icWcat, *H1, *H2, *CT, *Z01, *cb01;
    cudaGetSymbolAddress((void**)&Pt,     g_Pt);
    cudaGetSymbolAddress((void**)&PtSc,   g_PtSc);
    cudaGetSymbolAddress((void**)&Lm,     g_Lm);
    cudaGetSymbolAddress((void**)&Hu,     g_Hu);
    cudaGetSymbolAddress((void**)&st,     g_st);
    cudaGetSymbolAddress((void**)&G1,     g_G1);
    cudaGetSymbolAddress((void**)&icWcat, g_icWcat);
    cudaGetSymbolAddress((void**)&H1,     g_H1);
    cudaGetSymbolAddress((void**)&H2,     g_H2);
    cudaGetSymbolAddress((void**)&CT,     g_CT);
    cudaGetSymbolAddress((void**)&Z01,    g_Z01);
    cudaGetSymbolAddress((void**)&cb01,   g_cb01);

    constexpr int LDS = 20, STAGES = 4;
    const int smem64x128  = STAGES*(64 +128)*LDS*4;   // 61440
    const int smem128x128 = STAGES*(128+128)*LDS*4;   // 81920
    const int smem64x64   = STAGES*(64 + 64)*LDS*4;   // 40960
    cudaFuncSetAttribute(mmaGemm<64,128,0>,  cudaFuncAttributeMaxDynamicSharedMemorySize, smem64x128);
    cudaFuncSetAttribute(mmaGemm<128,128,0>, cudaFuncAttributeMaxDynamicSharedMemorySize, smem128x128);
    cudaFuncSetAttribute(mmaGemm<128,128,1>, cudaFuncAttributeMaxDynamicSharedMemorySize, smem128x128);
    cudaFuncSetAttribute(mmaGemm<64,64,0>,   cudaFuncAttributeMaxDynamicSharedMemorySize, smem64x64);

    transposePK<<<dim3(32,32), dim3(32,8)>>>(P, t, Pt, PtSc);
    catIcWK<<<(64*DIN2)/256, 256>>>(icW0, icW1);
    prepIcnnK<<<1, 256>>>(icU0, icU1, icb0, icb1, icb2);
    huStK<<<(NROWS*512)/256, 256>>>(state);

    // Lm = PtSc @ Pt^T        (1024 x 1024 x 1024)
    mmaGemm<64,128,0><<<dim3(1024/128, 1024/64), 256, smem64x128>>>(1024, 1024, 1024, PtSc, Pt, nullptr, Lm);
    // G1 = Hu @ Lm (symmetric) (4096 x 1024 x 1024)
    mmaGemm<128,128,0><<<dim3(1024/128, NROWS/128), 256, smem128x128>>>(NROWS, 1024, 1024, Hu, Lm, nullptr, G1);
    // H1 = tanh(st @ W1^T + b1)   (4096 x 512 x 2048)
    mmaGemm<128,128,1><<<dim3(512/128, NROWS/128), 256, smem128x128>>>(NROWS, 512, 2048, st, W1, b1, H1);
    // H2 = tanh(H1 @ W2^T + b2)   (4096 x 512 x 512)
    mmaGemm<128,128,1><<<dim3(512/128, NROWS/128), 256, smem128x128>>>(NROWS, 512, 512, H1, W2, b2, H2);
    // CT = H2 @ W3^T + b3         (4096 x 2048 x 512)
    mmaGemm<128,128,0><<<dim3(2048/128, NROWS/128), 256, smem128x128>>>(NROWS, 2048, 512, H2, W3, b3, CT);
    // Z01 = state @ icWcat^T + cb01  (4096 x 128 x 2048)
    mmaGemm<64,64,0><<<dim3(128/64, NROWS/64), 256, smem64x64>>>(NROWS, 128, 2048, state, icWcat, cb01, Z01);

    z2K<<<NROWS/4, 256>>>();
    finalK<<<NROWS, 256>>>(state, icW2, icb2, out);
}